// round 9
// baseline (speedup 1.0000x reference)
#include <cuda_runtime.h>
#include <cuda_fp16.h>
#include <cstdint>

#define BATCH 512
#define SEQLEN 512
#define INSZ 64
#define RES 1024
#define OUTSZ 64

// ---------------- static device buffers (no allocation allowed) -------------
__device__ float g_state[BATCH * RES];              // fp32 state, in-place
__device__ __half g_shi[2][BATCH * RES];            // state hi (fp16), ping-pong
__device__ __half g_slo[2][BATCH * RES];            // state lo (fp16), ping-pong
__device__ __half g_w16[RES * RES];                 // W_res in fp16
__device__ __half g_win16[INSZ * RES];              // W_in in fp16
__device__ __half g_xhi[BATCH * SEQLEN * INSZ];     // input hi
__device__ __half g_xlo[BATCH * SEQLEN * INSZ];     // input lo

// ---------------- merged prep kernel (ONE launch) ---------------------------
__global__ void prep_kernel(const float* __restrict__ input,
                            const float* __restrict__ Wres,
                            const float* __restrict__ Win) {
    int i = blockIdx.x * blockDim.x + threadIdx.x;
    int stride = gridDim.x * blockDim.x;
    const __half z = __float2half(0.0f);
    for (int k = i; k < BATCH * SEQLEN * INSZ; k += stride) {
        float v = input[k];
        __half h = __float2half(v);
        g_xhi[k] = h;
        g_xlo[k] = __float2half(v - __half2float(h));
        if (k < RES * RES) g_w16[k] = __float2half(Wres[k]);
        if (k < INSZ * RES) g_win16[k] = __float2half(Win[k]);
        if (k < BATCH * RES) {
            g_state[k] = 0.0f;
            g_shi[0][k] = z;
            g_slo[0][k] = z;
        }
    }
}

// ---------------- fast tanh (ex2 + rcp approx; abs err ~1e-6) ---------------
__device__ __forceinline__ float fast_tanhf(float x) {
    float e;
    asm("ex2.approx.f32 %0, %1;" : "=f"(e) : "f"(x * 2.8853900817779268f)); // 2x*log2(e)
    float r;
    asm("rcp.approx.f32 %0, %1;" : "=f"(r) : "f"(e + 1.0f));
    return fmaf(-2.0f, r, 1.0f);            // 1 - 2/(e^{2x}+1)
}

// ---------------- step kernel ----------------------------------------------
// Y = Shi@W16 + Slo@W16 + xhi@Win16 + xlo@Win16 (2-product fp16 split).
// BK=128 K-blocks (8 of state/W + 1 half-size input/Win) = 9 iterations.
// BM=BN=64, 512 threads (16 warps, 4Mx4N, warp tile 16x16), 3-slot ring.
// 4 warps per SMSP -> latency hiding for ldmatrix/mma chains (r8 profile:
// occ 12.3%, issue 27.9%, nothing saturated => latency-bound at 2 warps/SMSP).
#define NIT 9
#define NSLOT 3
#define STAGE_BYTES 49152      // Ahi 16K | Alo 16K | B 16K
#define A_LO_OFF 16384
#define B_OFF    32768

__device__ __forceinline__ uint32_t sw_off(int row, int colByte) {
    // 128B rows, XOR-swizzled 16B chunks: conflict-free cp.async + ldmatrix
    return (uint32_t)(row * 128 + ((((colByte >> 4) ^ (row & 7)) << 4) | (colByte & 15)));
}

__global__ __launch_bounds__(512) void step_kernel(int t) {
    extern __shared__ char smem[];
    const int tid  = threadIdx.x;
    const int lane = tid & 31;
    const int warp = tid >> 5;
    const int warpM = warp & 3;     // 4 warps along M (16 rows each)
    const int warpN = warp >> 2;    // 4 warps along N (16 cols each)
    const int rowBase = blockIdx.y * 64;   // batch rows
    const int colBase = blockIdx.x * 64;   // reservoir cols
    const int pp = t & 1;

    const uint32_t smem_u32 = (uint32_t)__cvta_generic_to_shared(smem);

    // issue K-block kk into slot kk%3.  kk<8: BK=128 state/W.  kk==8: BK=64 input.
    auto issue = [&](int kk) {
        const __half *Ahi, *Alo, *B;
        long long ldA;
        int kch;                                   // 16B chunks per A row (BK/8)
        if (kk < 8) {
            int k0 = kk << 7;
            Ahi = g_shi[pp] + k0;
            Alo = g_slo[pp] + k0;
            ldA = RES;
            B = g_w16 + (long long)k0 * RES;
            kch = 16;
        } else {
            Ahi = g_xhi + (long long)t * INSZ;
            Alo = g_xlo + (long long)t * INSZ;
            ldA = (long long)SEQLEN * INSZ;
            B = g_win16;
            kch = 8;
        }
        uint32_t base = smem_u32 + (kk % NSLOT) * STAGE_BYTES;
        const int nl = kch >> 3;                   // 2 (BK=128) or 1 (BK=64)
        for (int i = 0; i < nl; i++) {             // A tiles: 64 rows x kch chunks
            int c = tid + i * 512;
            int r = c / kch, kc = c % kch;
            uint32_t so = (uint32_t)(kc >> 3) * 8192 + sw_off(r, (kc & 7) * 16);
            long long aoff = (long long)(rowBase + r) * ldA + kc * 8;
            asm volatile("cp.async.cg.shared.global [%0], [%1], 16;\n"
                         :: "r"(base + so), "l"((const void*)(Ahi + aoff)));
            asm volatile("cp.async.cg.shared.global [%0], [%1], 16;\n"
                         :: "r"(base + A_LO_OFF + so), "l"((const void*)(Alo + aoff)));
        }
        for (int i = 0; i < nl; i++) {             // B tile: BK rows x 8 chunks
            int c = tid + i * 512;
            int kr = c >> 3, nc = c & 7;
            uint32_t so = (uint32_t)(kr >> 6) * 8192 + sw_off(kr & 63, nc * 16);
            long long boff = (long long)kr * RES + colBase + nc * 8;
            asm volatile("cp.async.cg.shared.global [%0], [%1], 16;\n"
                         :: "r"(base + B_OFF + so), "l"((const void*)(B + boff)));
        }
    };

    float acc[2][4];                 // warp tile 16x16: 2 n8 groups x 4 regs
    #pragma unroll
    for (int j = 0; j < 2; j++)
        #pragma unroll
        for (int q = 0; q < 4; q++) acc[j][q] = 0.0f;

    issue(0); asm volatile("cp.async.commit_group;\n" ::);
    issue(1); asm volatile("cp.async.commit_group;\n" ::);

    for (int kk = 0; kk < NIT; kk++) {
        asm volatile("cp.async.wait_group %0;\n" :: "n"(1));  // slot kk resident
        __syncthreads();            // all warps done with slot (kk-1)%3 reads
        if (kk + 2 < NIT) issue(kk + 2);
        asm volatile("cp.async.commit_group;\n" ::);

        uint32_t base = smem_u32 + (kk % NSLOT) * STAGE_BYTES;
        const int nkf = (kk < 8) ? 8 : 4;

        #pragma unroll 8
        for (int kf = 0; kf < nkf; kf++) {       // k16 slices
            const uint32_t sub = (uint32_t)(kf >> 2) * 8192;
            const int kfl = kf & 3;
            uint32_t ahi[4], alo[4];
            {
                int row = warpM * 16 + (lane & 15);
                int colByte = kfl * 32 + (lane >> 4) * 16;
                uint32_t so = sw_off(row, colByte);
                asm volatile("ldmatrix.sync.aligned.m8n8.x4.shared.b16 {%0,%1,%2,%3}, [%4];"
                    : "=r"(ahi[0]), "=r"(ahi[1]), "=r"(ahi[2]), "=r"(ahi[3])
                    : "r"(base + sub + so));
                asm volatile("ldmatrix.sync.aligned.m8n8.x4.shared.b16 {%0,%1,%2,%3}, [%4];"
                    : "=r"(alo[0]), "=r"(alo[1]), "=r"(alo[2]), "=r"(alo[3])
                    : "r"(base + A_LO_OFF + sub + so));
            }
            uint32_t b[4];                        // one n16 (warp's 16 cols)
            {
                int krow = kfl * 16 + (lane & 7) + ((lane >> 3) & 1) * 8;
                int colByte = (warpN * 16 + (lane >> 4) * 8) * 2;
                uint32_t so = sw_off(krow, colByte);
                asm volatile("ldmatrix.sync.aligned.m8n8.x4.trans.shared.b16 {%0,%1,%2,%3}, [%4];"
                    : "=r"(b[0]), "=r"(b[1]), "=r"(b[2]), "=r"(b[3])
                    : "r"(base + B_OFF + sub + so));
            }
            #pragma unroll
            for (int j = 0; j < 2; j++) {
                uint32_t b0 = b[j * 2], b1 = b[j * 2 + 1];
                asm volatile(
                    "mma.sync.aligned.m16n8k16.row.col.f32.f16.f16.f32 "
                    "{%0,%1,%2,%3}, {%4,%5,%6,%7}, {%8,%9}, {%0,%1,%2,%3};"
                    : "+f"(acc[j][0]), "+f"(acc[j][1]), "+f"(acc[j][2]), "+f"(acc[j][3])
                    : "r"(ahi[0]), "r"(ahi[1]), "r"(ahi[2]), "r"(ahi[3]), "r"(b0), "r"(b1));
                asm volatile(
                    "mma.sync.aligned.m16n8k16.row.col.f32.f16.f16.f32 "
                    "{%0,%1,%2,%3}, {%4,%5,%6,%7}, {%8,%9}, {%0,%1,%2,%3};"
                    : "+f"(acc[j][0]), "+f"(acc[j][1]), "+f"(acc[j][2]), "+f"(acc[j][3])
                    : "r"(alo[0]), "r"(alo[1]), "r"(alo[2]), "r"(alo[3]), "r"(b0), "r"(b1));
            }
        }
    }

    // ---- epilogue: leaky tanh; in-place fp32 state (tile-exclusive),
    //      emit fp16 hi/lo for next step ----
    __half* __restrict__ shiN = g_shi[pp ^ 1];
    __half* __restrict__ sloN = g_slo[pp ^ 1];
    #pragma unroll
    for (int j = 0; j < 2; j++)
        #pragma unroll
        for (int h = 0; h < 2; h++) {
            int row = rowBase + warpM * 16 + (lane >> 2) + 8 * h;
            int col = colBase + warpN * 16 + j * 8 + (lane & 3) * 2;
            long long idx = (long long)row * RES + col;
            float2 sold = *reinterpret_cast<float2*>(&g_state[idx]);
            float n0 = 0.5f * sold.x + 0.5f * fast_tanhf(acc[j][h * 2 + 0]);
            float n1 = 0.5f * sold.y + 0.5f * fast_tanhf(acc[j][h * 2 + 1]);
            *reinterpret_cast<float2*>(&g_state[idx]) = make_float2(n0, n1);
            __half h0 = __float2half(n0);
            __half h1 = __float2half(n1);
            __half2 hv; hv.x = h0; hv.y = h1;
            __half2 lv;
            lv.x = __float2half(n0 - __half2float(h0));
            lv.y = __float2half(n1 - __half2float(h1));
            *reinterpret_cast<__half2*>(&shiN[idx]) = hv;
            *reinterpret_cast<__half2*>(&sloN[idx]) = lv;
        }
}

// ---------------- output GEMM ----------------------------------------------
__global__ __launch_bounds__(64) void output_kernel(
    const float* __restrict__ Wout, float* __restrict__ out) {
    __shared__ float srow[RES];
    const int b = blockIdx.x;
    const int j = threadIdx.x;
    for (int k = j; k < RES; k += 64) srow[k] = g_state[b * RES + k];
    __syncthreads();
    float sum = 0.0f;
    #pragma unroll 8
    for (int k = 0; k < RES; k++)
        sum = fmaf(srow[k], Wout[k * OUTSZ + j], sum);
    out[b * OUTSZ + j] = sum;
}

// ---------------- launch ----------------------------------------------------
extern "C" void kernel_launch(void* const* d_in, const int* in_sizes, int n_in,
                              void* d_out, int out_size) {
    const float* input = (const float*)d_in[0];   // [512,512,64]
    const float* Wres  = (const float*)d_in[1];   // [1024,1024]
    const float* Win   = (const float*)d_in[2];   // [64,1024]
    const float* Wout  = (const float*)d_in[3];   // [1024,64]
    float* out = (float*)d_out;

    cudaFuncSetAttribute(step_kernel,
                         cudaFuncAttributeMaxDynamicSharedMemorySize,
                         NSLOT * STAGE_BYTES);

    prep_kernel<<<4096, 256>>>(input, Wres, Win);   // my-index 0

    dim3 grid(RES / 64, BATCH / 64);   // (16, 8) = 128 CTAs
    for (int t = 0; t < SEQLEN; t++)   // my-index 1..512 (t=2 -> ncu slot 5)
        step_kernel<<<grid, 512, NSLOT * STAGE_BYTES>>>(t);

    output_kernel<<<BATCH, 64>>>(Wout, out);
}

// round 10
// speedup vs baseline: 1.1991x; 1.1991x over previous
#include <cuda_runtime.h>
#include <cuda.h>
#include <cuda_fp16.h>
#include <cstdint>

#define BATCH 512
#define SEQLEN 512
#define INSZ 64
#define RES 1024
#define OUTSZ 64

// ---------------- static device buffers (no allocation allowed) -------------
__device__ float g_state[BATCH * RES];              // fp32 state, in-place
__device__ __half g_shi[2][BATCH * RES];            // state hi (fp16), ping-pong
__device__ __half g_slo[2][BATCH * RES];            // state lo (fp16), ping-pong
__device__ __half g_w16[RES * RES];                 // W_res in fp16
__device__ __half g_win16[INSZ * RES];              // W_in in fp16
__device__ __half g_xhi[BATCH * SEQLEN * INSZ];     // input hi
__device__ __half g_xlo[BATCH * SEQLEN * INSZ];     // input lo

struct TMaps {
    CUtensorMap shi[2];
    CUtensorMap slo[2];
    CUtensorMap w;
    CUtensorMap win;
    CUtensorMap xhi;
    CUtensorMap xlo;
};

// ---------------- merged prep kernel (ONE launch) ---------------------------
__global__ void prep_kernel(const float* __restrict__ input,
                            const float* __restrict__ Wres,
                            const float* __restrict__ Win) {
    int i = blockIdx.x * blockDim.x + threadIdx.x;
    int stride = gridDim.x * blockDim.x;
    const __half z = __float2half(0.0f);
    for (int k = i; k < BATCH * SEQLEN * INSZ; k += stride) {
        float v = input[k];
        __half h = __float2half(v);
        g_xhi[k] = h;
        g_xlo[k] = __float2half(v - __half2float(h));
        if (k < RES * RES) g_w16[k] = __float2half(Wres[k]);
        if (k < INSZ * RES) g_win16[k] = __float2half(Win[k]);
        if (k < BATCH * RES) {
            g_state[k] = 0.0f;
            g_shi[0][k] = z;
            g_slo[0][k] = z;
        }
    }
}

// ---------------- fast tanh (ex2 + rcp approx; abs err ~1e-6) ---------------
__device__ __forceinline__ float fast_tanhf(float x) {
    float e;
    asm("ex2.approx.f32 %0, %1;" : "=f"(e) : "f"(x * 2.8853900817779268f)); // 2x*log2(e)
    float r;
    asm("rcp.approx.f32 %0, %1;" : "=f"(r) : "f"(e + 1.0f));
    return fmaf(-2.0f, r, 1.0f);            // 1 - 2/(e^{2x}+1)
}

// ---------------- PTX helpers ------------------------------------------------
#define MBARRIER_INIT(addr, cnt) \
    asm volatile("mbarrier.init.shared.b64 [%0], %1;" :: "r"(addr), "r"(cnt) : "memory")

#define MBARRIER_EXPECT_TX(addr, bytes) \
    asm volatile("mbarrier.arrive.expect_tx.shared.b64 _, [%0], %1;" \
                 :: "r"(addr), "r"(bytes) : "memory")

#define MBARRIER_WAIT_PARITY(mbar, par) do {                                   \
    uint32_t _m = (mbar); uint32_t _p = (par); uint32_t _done;                 \
    asm volatile("{\n\t.reg .pred p;\n\t"                                      \
        "mbarrier.try_wait.parity.acquire.cta.shared::cta.b64 p, [%1], %2;\n\t"\
        "selp.b32 %0, 1, 0, p;\n\t}" : "=r"(_done) : "r"(_m), "r"(_p) : "memory"); \
    if (!_done) {                                                              \
        asm volatile("{\n\t.reg .pred P1;\n\tWL_%=:\n\t"                       \
            "mbarrier.try_wait.parity.acquire.cta.shared::cta.b64 P1, [%0], %1, 0x989680;\n\t" \
            "@P1 bra.uni WD_%=;\n\tbra.uni WL_%=;\n\tWD_%=:\n\t}"              \
            :: "r"(_m), "r"(_p) : "memory");                                   \
    }                                                                          \
} while (0)

__device__ __forceinline__ void tma2d(uint32_t dst, const CUtensorMap* m,
                                      int c0, int c1, uint32_t mbar) {
    asm volatile(
        "cp.async.bulk.tensor.2d.shared::cluster.global.tile.mbarrier::complete_tx::bytes "
        "[%0], [%1, {%2, %3}], [%4];"
        :: "r"(dst), "l"(m), "r"(c0), "r"(c1), "r"(mbar) : "memory");
}

__device__ __forceinline__ void tma3d(uint32_t dst, const CUtensorMap* m,
                                      int c0, int c1, int c2, uint32_t mbar) {
    asm volatile(
        "cp.async.bulk.tensor.3d.shared::cluster.global.tile.mbarrier::complete_tx::bytes "
        "[%0], [%1, {%2, %3, %4}], [%5];"
        :: "r"(dst), "l"(m), "r"(c0), "r"(c1), "r"(c2), "r"(mbar) : "memory");
}

// ---------------- step kernel ----------------------------------------------
// Y = Shi@W16 + Slo@W16 + xhi@Win16 + xlo@Win16 (2-product fp16 split).
// BK=128 K-blocks (8 of state/W + 1 half-size input/Win) = 9 iterations.
// TMA loads (6 per stage, one elected thread) replace 3072 cp.async issues:
// r9 profile showed MIO-issue-bound (issue 33%, tensor 20%, nothing saturated).
// BM=BN=64, 256 threads (8 warps, 4Mx2N, warp tile 16x32), 3-slot ring,
// per-slot mbarrier with expect_tx.
#define NIT 9
#define NSLOT 3
#define STAGE_BYTES 49152      // Ahi 16K | Alo 16K | B 16K
#define A_LO_OFF 16384
#define B_OFF    32768

__device__ __forceinline__ uint32_t sw_off(int row, int colByte) {
    // 128B rows, XOR-swizzled 16B chunks == TMA SW128 atom layout
    return (uint32_t)(row * 128 + ((((colByte >> 4) ^ (row & 7)) << 4) | (colByte & 15)));
}

__global__ __launch_bounds__(256) void step_kernel(
    const __grid_constant__ TMaps tm, int t) {
    extern __shared__ __align__(1024) char smem[];
    __shared__ __align__(8) uint64_t s_mbar[NSLOT];

    const int tid  = threadIdx.x;
    const int lane = tid & 31;
    const int warp = tid >> 5;
    const int warpM = warp & 3;     // 4 warps along M (16 rows each)
    const int warpN = warp >> 2;    // 2 warps along N (32 cols each)
    const int rowBase = blockIdx.y * 64;   // batch rows
    const int colBase = blockIdx.x * 64;   // reservoir cols
    const int pp = t & 1;

    const uint32_t smem_u32 = (uint32_t)__cvta_generic_to_shared(smem);
    const uint32_t mbar0    = (uint32_t)__cvta_generic_to_shared(s_mbar);

    const CUtensorMap* mShi = &tm.shi[pp];
    const CUtensorMap* mSlo = &tm.slo[pp];

    if (tid == 0) {
        #pragma unroll
        for (int s = 0; s < NSLOT; s++) MBARRIER_INIT(mbar0 + s * 8, 1);
    }
    __syncthreads();

    // issue K-block kk into slot kk%3 (tid 0 only)
    auto issue = [&](int kk) {
        uint32_t base = smem_u32 + (kk % NSLOT) * STAGE_BYTES;
        uint32_t mb   = mbar0 + (kk % NSLOT) * 8;
        if (kk < 8) {
            int k0 = kk << 7;
            MBARRIER_EXPECT_TX(mb, 49152u);
            tma2d(base,                 mShi, k0,      rowBase, mb);
            tma2d(base + 8192,          mShi, k0 + 64, rowBase, mb);
            tma2d(base + A_LO_OFF,        mSlo, k0,      rowBase, mb);
            tma2d(base + A_LO_OFF + 8192, mSlo, k0 + 64, rowBase, mb);
            tma2d(base + B_OFF,         &tm.w, colBase, k0,      mb);
            tma2d(base + B_OFF + 8192,  &tm.w, colBase, k0 + 64, mb);
        } else {
            MBARRIER_EXPECT_TX(mb, 24576u);
            tma3d(base,            &tm.xhi, 0, t, rowBase, mb);
            tma3d(base + A_LO_OFF, &tm.xlo, 0, t, rowBase, mb);
            tma2d(base + B_OFF,    &tm.win, colBase, 0, mb);
        }
    };

    if (tid == 0) { issue(0); issue(1); }

    float acc[4][4];                 // warp tile 16x32: 4 n8 groups x 4 regs
    #pragma unroll
    for (int j = 0; j < 4; j++)
        #pragma unroll
        for (int q = 0; q < 4; q++) acc[j][q] = 0.0f;

    for (int kk = 0; kk < NIT; kk++) {
        __syncthreads();             // all warps done reading slot (kk+2)%3
        if (tid == 0 && kk + 2 < NIT) issue(kk + 2);
        MBARRIER_WAIT_PARITY(mbar0 + (kk % NSLOT) * 8, (uint32_t)((kk / 3) & 1));

        uint32_t base = smem_u32 + (kk % NSLOT) * STAGE_BYTES;
        const int nkf = (kk < 8) ? 8 : 4;

        #pragma unroll 8
        for (int kf = 0; kf < nkf; kf++) {       // k16 slices
            const uint32_t sub = (uint32_t)(kf >> 2) * 8192;
            const int kfl = kf & 3;
            uint32_t ahi[4], alo[4];
            {
                int row = warpM * 16 + (lane & 15);
                int colByte = kfl * 32 + (lane >> 4) * 16;
                uint32_t so = sw_off(row, colByte);
                asm volatile("ldmatrix.sync.aligned.m8n8.x4.shared.b16 {%0,%1,%2,%3}, [%4];"
                    : "=r"(ahi[0]), "=r"(ahi[1]), "=r"(ahi[2]), "=r"(ahi[3])
                    : "r"(base + sub + so));
                asm volatile("ldmatrix.sync.aligned.m8n8.x4.shared.b16 {%0,%1,%2,%3}, [%4];"
                    : "=r"(alo[0]), "=r"(alo[1]), "=r"(alo[2]), "=r"(alo[3])
                    : "r"(base + A_LO_OFF + sub + so));
            }
            uint32_t b[2][4];
            #pragma unroll
            for (int nh = 0; nh < 2; nh++) {
                int krow = kfl * 16 + (lane & 7) + ((lane >> 3) & 1) * 8;
                int colByte = (warpN * 32 + nh * 16 + (lane >> 4) * 8) * 2;
                uint32_t so = sw_off(krow, colByte);
                asm volatile("ldmatrix.sync.aligned.m8n8.x4.trans.shared.b16 {%0,%1,%2,%3}, [%4];"
                    : "=r"(b[nh][0]), "=r"(b[nh][1]), "=r"(b[nh][2]), "=r"(b[nh][3])
                    : "r"(base + B_OFF + sub + so));
            }
            #pragma unroll
            for (int j = 0; j < 4; j++) {
                uint32_t b0 = b[j >> 1][(j & 1) * 2], b1 = b[j >> 1][(j & 1) * 2 + 1];
                asm volatile(
                    "mma.sync.aligned.m16n8k16.row.col.f32.f16.f16.f32 "
                    "{%0,%1,%2,%3}, {%4,%5,%6,%7}, {%8,%9}, {%0,%1,%2,%3};"
                    : "+f"(acc[j][0]), "+f"(acc[j][1]), "+f"(acc[j][2]), "+f"(acc[j][3])
                    : "r"(ahi[0]), "r"(ahi[1]), "r"(ahi[2]), "r"(ahi[3]), "r"(b0), "r"(b1));
                asm volatile(
                    "mma.sync.aligned.m16n8k16.row.col.f32.f16.f16.f32 "
                    "{%0,%1,%2,%3}, {%4,%5,%6,%7}, {%8,%9}, {%0,%1,%2,%3};"
                    : "+f"(acc[j][0]), "+f"(acc[j][1]), "+f"(acc[j][2]), "+f"(acc[j][3])
                    : "r"(alo[0]), "r"(alo[1]), "r"(alo[2]), "r"(alo[3]), "r"(b0), "r"(b1));
            }
        }
    }

    // ---- epilogue: leaky tanh; in-place fp32 state (tile-exclusive),
    //      emit fp16 hi/lo for next step ----
    __half* __restrict__ shiN = g_shi[pp ^ 1];
    __half* __restrict__ sloN = g_slo[pp ^ 1];
    #pragma unroll
    for (int j = 0; j < 4; j++)
        #pragma unroll
        for (int h = 0; h < 2; h++) {
            int row = rowBase + warpM * 16 + (lane >> 2) + 8 * h;
            int col = colBase + warpN * 32 + j * 8 + (lane & 3) * 2;
            long long idx = (long long)row * RES + col;
            float2 sold = *reinterpret_cast<float2*>(&g_state[idx]);
            float n0 = 0.5f * sold.x + 0.5f * fast_tanhf(acc[j][h * 2 + 0]);
            float n1 = 0.5f * sold.y + 0.5f * fast_tanhf(acc[j][h * 2 + 1]);
            *reinterpret_cast<float2*>(&g_state[idx]) = make_float2(n0, n1);
            __half h0 = __float2half(n0);
            __half h1 = __float2half(n1);
            __half2 hv; hv.x = h0; hv.y = h1;
            __half2 lv;
            lv.x = __float2half(n0 - __half2float(h0));
            lv.y = __float2half(n1 - __half2float(h1));
            *reinterpret_cast<__half2*>(&shiN[idx]) = hv;
            *reinterpret_cast<__half2*>(&sloN[idx]) = lv;
        }
}

// ---------------- output GEMM ----------------------------------------------
__global__ __launch_bounds__(64) void output_kernel(
    const float* __restrict__ Wout, float* __restrict__ out) {
    __shared__ float srow[RES];
    const int b = blockIdx.x;
    const int j = threadIdx.x;
    for (int k = j; k < RES; k += 64) srow[k] = g_state[b * RES + k];
    __syncthreads();
    float sum = 0.0f;
    #pragma unroll 8
    for (int k = 0; k < RES; k++)
        sum = fmaf(srow[k], Wout[k * OUTSZ + j], sum);
    out[b * OUTSZ + j] = sum;
}

// ---------------- host: tensormap construction ------------------------------
typedef CUresult (*EncodeFn)(CUtensorMap*, CUtensorMapDataType, cuuint32_t, void*,
                             const cuuint64_t*, const cuuint64_t*, const cuuint32_t*,
                             const cuuint32_t*, CUtensorMapInterleave, CUtensorMapSwizzle,
                             CUtensorMapL2promotion, CUtensorMapFloatOOBfill);

static EncodeFn get_encode_fn() {
    void* p = nullptr;
#if CUDART_VERSION >= 12050
    cudaDriverEntryPointQueryResult st;
    cudaGetDriverEntryPointByVersion("cuTensorMapEncodeTiled", &p, 12000,
                                     cudaEnableDefault, &st);
#else
    cudaDriverEntryPointQueryResult st;
    cudaGetDriverEntryPoint("cuTensorMapEncodeTiled", &p, cudaEnableDefault, &st);
#endif
    return (EncodeFn)p;
}

static void enc2d(EncodeFn f, CUtensorMap* m, void* ptr,
                  uint64_t d0, uint64_t d1, uint64_t stride1B) {
    cuuint64_t dims[2] = {d0, d1};
    cuuint64_t strides[1] = {stride1B};
    cuuint32_t box[2] = {64, 64};
    cuuint32_t es[2] = {1, 1};
    f(m, CU_TENSOR_MAP_DATA_TYPE_FLOAT16, 2, ptr, dims, strides, box, es,
      CU_TENSOR_MAP_INTERLEAVE_NONE, CU_TENSOR_MAP_SWIZZLE_128B,
      CU_TENSOR_MAP_L2_PROMOTION_L2_128B, CU_TENSOR_MAP_FLOAT_OOB_FILL_NONE);
}

static void enc3d_x(EncodeFn f, CUtensorMap* m, void* ptr) {
    cuuint64_t dims[3] = {INSZ, SEQLEN, BATCH};
    cuuint64_t strides[2] = {INSZ * 2ull, (uint64_t)SEQLEN * INSZ * 2ull};
    cuuint32_t box[3] = {64, 1, 64};
    cuuint32_t es[3] = {1, 1, 1};
    f(m, CU_TENSOR_MAP_DATA_TYPE_FLOAT16, 3, ptr, dims, strides, box, es,
      CU_TENSOR_MAP_INTERLEAVE_NONE, CU_TENSOR_MAP_SWIZZLE_128B,
      CU_TENSOR_MAP_L2_PROMOTION_L2_128B, CU_TENSOR_MAP_FLOAT_OOB_FILL_NONE);
}

// ---------------- launch ----------------------------------------------------
extern "C" void kernel_launch(void* const* d_in, const int* in_sizes, int n_in,
                              void* d_out, int out_size) {
    const float* input = (const float*)d_in[0];   // [512,512,64]
    const float* Wres  = (const float*)d_in[1];   // [1024,1024]
    const float* Win   = (const float*)d_in[2];   // [64,1024]
    const float* Wout  = (const float*)d_in[3];   // [1024,64]
    float* out = (float*)d_out;

    void *shi, *slo, *w16, *win16, *xhi, *xlo;
    cudaGetSymbolAddress(&shi,   g_shi);
    cudaGetSymbolAddress(&slo,   g_slo);
    cudaGetSymbolAddress(&w16,   g_w16);
    cudaGetSymbolAddress(&win16, g_win16);
    cudaGetSymbolAddress(&xhi,   g_xhi);
    cudaGetSymbolAddress(&xlo,   g_xlo);

    EncodeFn enc = get_encode_fn();
    TMaps tm;
    // state: [M=512 rows, K=1024 cols] fp16, dim0 = K (contiguous)
    enc2d(enc, &tm.shi[0], shi, RES, BATCH, RES * 2ull);
    enc2d(enc, &tm.shi[1], (char*)shi + (size_t)BATCH * RES * 2, RES, BATCH, RES * 2ull);
    enc2d(enc, &tm.slo[0], slo, RES, BATCH, RES * 2ull);
    enc2d(enc, &tm.slo[1], (char*)slo + (size_t)BATCH * RES * 2, RES, BATCH, RES * 2ull);
    // W: [K=1024 rows, N=1024 cols], dim0 = N (contiguous)
    enc2d(enc, &tm.w, w16, RES, RES, RES * 2ull);
    // Win: [K=64 rows, N=1024 cols]
    enc2d(enc, &tm.win, win16, RES, INSZ, RES * 2ull);
    // x: [B, T, I] -> 3D {I, T, B}
    enc3d_x(enc, &tm.xhi, xhi);
    enc3d_x(enc, &tm.xlo, xlo);

    cudaFuncSetAttribute(step_kernel,
                         cudaFuncAttributeMaxDynamicSharedMemorySize,
                         NSLOT * STAGE_BYTES);

    prep_kernel<<<4096, 256>>>(input, Wres, Win);   // my-index 0

    dim3 grid(RES / 64, BATCH / 64);   // (16, 8) = 128 CTAs
    for (int t = 0; t < SEQLEN; t++)   // my-index 1..512 (t=2 -> ncu slot 5)
        step_kernel<<<grid, 256, NSLOT * STAGE_BYTES>>>(tm, t);

    output_kernel<<<BATCH, 64>>>(Wout, out);
}